// round 1
// baseline (speedup 1.0000x reference)
#include <cuda_runtime.h>

#define T_LEN 4096
#define N_DIM 256
#define U_DIM 128
#define K_DIM 32
#define P_DIM 128
#define NK    8192   // N_DIM * K_DIM
#define CH_L  64     // chunk length
#define NCH   64     // number of chunks (T_LEN / CH_L)

// ---------------- device scratch (no runtime allocation allowed) ----------------
__device__ float g_S_re[(size_t)T_LEN * NK];   // 134 MB
__device__ float g_S_im[(size_t)T_LEN * NK];   // 134 MB
__device__ float g_Bt_re[U_DIM * N_DIM];
__device__ float g_Bt_im[U_DIM * N_DIM];
__device__ float g_Ct_re[N_DIM * P_DIM];
__device__ float g_Ct_im[N_DIM * P_DIM];
__device__ float g_Dt[U_DIM * P_DIM];
__device__ float g_send_re[NCH * NK];
__device__ float g_send_im[NCH * NK];
__device__ float g_carry_re[NCH * NK];
__device__ float g_carry_im[NCH * NK];
__device__ float g_apow_re[CH_L * NK];
__device__ float g_apow_im[CH_L * NK];

// ---------------- packed f32x2 helpers (Blackwell FFMA2) ----------------
typedef unsigned long long u64;

__device__ __forceinline__ u64 pack2(float x, float y) {
    u64 r;
    asm("mov.b64 %0, {%1, %2};" : "=l"(r) : "f"(x), "f"(y));
    return r;
}
__device__ __forceinline__ u64 ffma2(u64 a, u64 b, u64 c) {
    u64 d;
    asm("fma.rn.f32x2 %0, %1, %2, %3;" : "=l"(d) : "l"(a), "l"(b), "l"(c));
    return d;
}

// ---------------- K0: transpose small weight matrices ----------------
__global__ __launch_bounds__(256) void k0_transpose(
    const float* __restrict__ Bre, const float* __restrict__ Bim,
    const float* __restrict__ Cre, const float* __restrict__ Cim,
    const float* __restrict__ D)
{
    int i = blockIdx.x * 256 + threadIdx.x;
    if (i < N_DIM * U_DIM) {           // B: (N,U) -> Bt: (U,N)
        int n = i / U_DIM, u = i % U_DIM;
        g_Bt_re[u * N_DIM + n] = Bre[i];
        g_Bt_im[u * N_DIM + n] = Bim[i];
    }
    if (i < P_DIM * N_DIM) {           // C: (P,N) -> Ct: (N,P)
        int p = i / N_DIM, n = i % N_DIM;
        g_Ct_re[n * P_DIM + p] = Cre[i];
        g_Ct_im[n * P_DIM + p] = Cim[i];
    }
    if (i < P_DIM * U_DIM) {           // D: (P,U) -> Dt: (U,P)
        int p = i / U_DIM, u = i % U_DIM;
        g_Dt[u * P_DIM + p] = D[i];
    }
}

// ---------------- K1: S[t,n,k] = sum_u B[n,u] * x[t,u,k]  (complex = re+im) ----
// block = one timestep t; 256 threads; warp w: kh = w&3 (8 k's), nh = w>>2.
// thread owns n in {nh*128 + lane + 32j, j=0..3}, k pairs kb..kb+7.
__global__ __launch_bounds__(256) void k1_bproj(const float* __restrict__ x)
{
    __shared__ float Xs[U_DIM * K_DIM];       // 16 KB
    __shared__ float Bsh[2 * 16 * N_DIM];     // 32 KB (re rows then im rows)
    int t = blockIdx.x;
    int tid = threadIdx.x;

    const float4* xp = (const float4*)(x + (size_t)t * U_DIM * K_DIM);
    float4* xs4 = (float4*)Xs;
#pragma unroll
    for (int i = 0; i < 4; i++) xs4[tid + i * 256] = xp[tid + i * 256];

    int lane = tid & 31;
    int w = tid >> 5;
    int kh = w & 3;
    int nh = w >> 2;
    int nbase = nh * 128 + lane;
    int kb = kh * 8;

    u64 accR[4][4], accI[4][4];
#pragma unroll
    for (int j = 0; j < 4; j++)
#pragma unroll
        for (int q = 0; q < 4; q++) { accR[j][q] = 0ull; accI[j][q] = 0ull; }

    for (int ut = 0; ut < 8; ut++) {
        __syncthreads();
        const float4* br = (const float4*)(g_Bt_re + ut * 16 * N_DIM);
        const float4* bi = (const float4*)(g_Bt_im + ut * 16 * N_DIM);
        float4* b0 = (float4*)Bsh;
        float4* b1 = (float4*)(Bsh + 16 * N_DIM);
#pragma unroll
        for (int i = 0; i < 4; i++) {
            b0[tid + i * 256] = br[tid + i * 256];
            b1[tid + i * 256] = bi[tid + i * 256];
        }
        __syncthreads();
#pragma unroll
        for (int up = 0; up < 16; up++) {
            int u = ut * 16 + up;
            u64 xv[4];
#pragma unroll
            for (int q = 0; q < 4; q++)
                xv[q] = *(const u64*)&Xs[u * K_DIM + kb + 2 * q];
#pragma unroll
            for (int j = 0; j < 4; j++) {
                float bre = Bsh[up * N_DIM + nbase + 32 * j];
                float bim = Bsh[16 * N_DIM + up * N_DIM + nbase + 32 * j];
                u64 b2r = pack2(bre, bre);
                u64 b2i = pack2(bim, bim);
#pragma unroll
                for (int q = 0; q < 4; q++) {
                    accR[j][q] = ffma2(b2r, xv[q], accR[j][q]);
                    accI[j][q] = ffma2(b2i, xv[q], accI[j][q]);
                }
            }
        }
    }

    size_t tb = (size_t)t * NK;
#pragma unroll
    for (int j = 0; j < 4; j++) {
        int n = nbase + 32 * j;
#pragma unroll
        for (int q = 0; q < 4; q++) {
            *(u64*)&g_S_re[tb + n * K_DIM + kb + 2 * q] = accR[j][q];
            *(u64*)&g_S_im[tb + n * K_DIM + kb + 2 * q] = accI[j][q];
        }
    }
}

// ---------------- K2a: local (per-chunk) scans, in place -----------------------
// thread = (chunk, chain); chains coalesced across a warp at fixed t.
__global__ __launch_bounds__(256) void k2_local(
    const float* __restrict__ Are, const float* __restrict__ Aim)
{
    int c = blockIdx.x * 256 + threadIdx.x;   // chain = n*K + k
    int chunk = blockIdx.y;
    float ar = Are[c], ai = Aim[c];
    float sr = 0.f, si = 0.f;
    int base = chunk * CH_L * NK + c;
    for (int tg = 0; tg < CH_L; tg += 4) {
        float inr[4], ini[4];
#pragma unroll
        for (int j = 0; j < 4; j++) {
            inr[j] = g_S_re[base + j * NK];
            ini[j] = g_S_im[base + j * NK];
        }
#pragma unroll
        for (int j = 0; j < 4; j++) {
            float nr = fmaf(ar, sr, fmaf(-ai, si, inr[j]));
            float ni = fmaf(ar, si, fmaf(ai, sr, ini[j]));
            sr = nr; si = ni;
            g_S_re[base + j * NK] = sr;
            g_S_im[base + j * NK] = si;
        }
        base += 4 * NK;
    }
    g_send_re[chunk * NK + c] = sr;
    g_send_im[chunk * NK + c] = si;
}

// ---------------- K2b: power table a^(j+1) and cross-chunk carries -------------
__global__ __launch_bounds__(256) void k2_carry(
    const float* __restrict__ Are, const float* __restrict__ Aim)
{
    int c = blockIdx.x * 256 + threadIdx.x;
    float ar = Are[c], ai = Aim[c];
    float qr = ar, qi = ai;
    float a64r = 0.f, a64i = 0.f;
    for (int j = 0; j < CH_L; j++) {
        g_apow_re[j * NK + c] = qr;
        g_apow_im[j * NK + c] = qi;
        if (j == CH_L - 1) { a64r = qr; a64i = qi; }
        float tmp = qr * ar - qi * ai;
        qi = qr * ai + qi * ar;
        qr = tmp;
    }
    float cr = 0.f, ci = 0.f;
    for (int ch = 0; ch < NCH; ch++) {
        g_carry_re[ch * NK + c] = cr;
        g_carry_im[ch * NK + c] = ci;
        float sr = g_send_re[ch * NK + c], si = g_send_im[ch * NK + c];
        float tmp = fmaf(a64r, cr, fmaf(-a64i, ci, sr));
        ci = fmaf(a64r, ci, fmaf(a64i, cr, si));
        cr = tmp;
    }
}

// ---------------- K3: out[t,p,k] = Re(C @ s_t) + D @ x_t, scan fixup fused -----
// block = one t; 256 threads; warp w: kh = w&3 (k pairs), ph = w>>2 (p half).
// s_global = s_local + a^(tl+1) * carry[chunk]  (done while staging to shared)
__global__ __launch_bounds__(256) void k3_out(
    const float* __restrict__ x, float* __restrict__ out)
{
    extern __shared__ float smem[];
    float* Ssr = smem;              // 8192 floats
    float* Ssi = smem + 8192;       // 8192
    float* Xs  = smem + 16384;      // 4096
    float* Wre = smem + 20480;      // 4096 (C re tile / D tile low half)
    float* Wim = smem + 24576;      // 4096 (C im tile / D tile high half)

    int t = blockIdx.x;
    int tid = threadIdx.x;
    int chunk = t >> 6, tl = t & 63;
    int tb = t * NK;

    // fixup + stage states
#pragma unroll 4
    for (int ii = 0; ii < 32; ii++) {
        int i = tid + ii * 256;
        float lr = g_S_re[tb + i], li = g_S_im[tb + i];
        float pr = g_apow_re[tl * NK + i], pi = g_apow_im[tl * NK + i];
        float cr = g_carry_re[chunk * NK + i], ci = g_carry_im[chunk * NK + i];
        Ssr[i] = fmaf(pr, cr, fmaf(-pi, ci, lr));
        Ssi[i] = fmaf(pr, ci, fmaf(pi, cr, li));
    }
    // stage x tile
    const float4* xp = (const float4*)(x + (size_t)t * U_DIM * K_DIM);
    float4* xs4 = (float4*)Xs;
#pragma unroll
    for (int i = 0; i < 4; i++) xs4[tid + i * 256] = xp[tid + i * 256];

    int lane = tid & 31;
    int w = tid >> 5;
    int kh = w & 3;
    int ph = w >> 2;
    int kb = kh * 8;
    int pb = ph * 64 + lane;

    u64 acc[2][4];
#pragma unroll
    for (int j = 0; j < 2; j++)
#pragma unroll
        for (int q = 0; q < 4; q++) acc[j][q] = 0ull;

    // C projection: loop over n tiles of 32
    for (int nt = 0; nt < 8; nt++) {
        __syncthreads();
        const float4* cr4 = (const float4*)(g_Ct_re + nt * 32 * P_DIM);
        const float4* ci4 = (const float4*)(g_Ct_im + nt * 32 * P_DIM);
#pragma unroll
        for (int i = 0; i < 4; i++) {
            ((float4*)Wre)[tid + i * 256] = cr4[tid + i * 256];
            ((float4*)Wim)[tid + i * 256] = ci4[tid + i * 256];
        }
        __syncthreads();
#pragma unroll
        for (int r = 0; r < 32; r++) {
            int n = nt * 32 + r;
            u64 svr[4], svi[4];
#pragma unroll
            for (int q = 0; q < 4; q++) {
                svr[q] = *(const u64*)&Ssr[n * K_DIM + kb + 2 * q];
                svi[q] = *(const u64*)&Ssi[n * K_DIM + kb + 2 * q];
            }
#pragma unroll
            for (int j = 0; j < 2; j++) {
                float crv = Wre[r * P_DIM + pb + 32 * j];
                float civ = Wim[r * P_DIM + pb + 32 * j];
                u64 c2r = pack2(crv, crv);
                u64 c2i = pack2(-civ, -civ);
#pragma unroll
                for (int q = 0; q < 4; q++) {
                    acc[j][q] = ffma2(c2r, svr[q], acc[j][q]);
                    acc[j][q] = ffma2(c2i, svi[q], acc[j][q]);
                }
            }
        }
    }

    // D skip branch: u tiles of 64, staged into Wre..Wim (8192 contiguous floats)
    for (int ut = 0; ut < 2; ut++) {
        __syncthreads();
        const float4* d4 = (const float4*)(g_Dt + ut * 64 * P_DIM);
#pragma unroll
        for (int i = 0; i < 8; i++)
            ((float4*)Wre)[tid + i * 256] = d4[tid + i * 256];
        __syncthreads();
#pragma unroll
        for (int r = 0; r < 64; r++) {
            int u = ut * 64 + r;
            u64 xv[4];
#pragma unroll
            for (int q = 0; q < 4; q++)
                xv[q] = *(const u64*)&Xs[u * K_DIM + kb + 2 * q];
#pragma unroll
            for (int j = 0; j < 2; j++) {
                float dv = Wre[r * P_DIM + pb + 32 * j];
                u64 d2 = pack2(dv, dv);
#pragma unroll
                for (int q = 0; q < 4; q++)
                    acc[j][q] = ffma2(d2, xv[q], acc[j][q]);
            }
        }
    }

    size_t ob = (size_t)t * P_DIM * K_DIM;
#pragma unroll
    for (int j = 0; j < 2; j++) {
        int p = pb + 32 * j;
#pragma unroll
        for (int q = 0; q < 4; q++)
            *(u64*)&out[ob + p * K_DIM + kb + 2 * q] = acc[j][q];
    }
}

// ---------------- launch ----------------
extern "C" void kernel_launch(void* const* d_in, const int* in_sizes, int n_in,
                              void* d_out, int out_size)
{
    const float* x   = (const float*)d_in[0];
    const float* Are = (const float*)d_in[1];
    const float* Aim = (const float*)d_in[2];
    const float* Bre = (const float*)d_in[3];
    const float* Bim = (const float*)d_in[4];
    const float* Cre = (const float*)d_in[5];
    const float* Cim = (const float*)d_in[6];
    const float* D   = (const float*)d_in[7];
    float* out = (float*)d_out;

    k0_transpose<<<128, 256>>>(Bre, Bim, Cre, Cim, D);
    k1_bproj<<<T_LEN, 256>>>(x);
    dim3 g2(NK / 256, NCH);
    k2_local<<<g2, 256>>>(Are, Aim);
    k2_carry<<<NK / 256, 256>>>(Are, Aim);
    cudaFuncSetAttribute(k3_out, cudaFuncAttributeMaxDynamicSharedMemorySize, 114688);
    k3_out<<<T_LEN, 256, 114688>>>(x, out);
}

// round 3
// speedup vs baseline: 1.2507x; 1.2507x over previous
#include <cuda_runtime.h>
#include <cuda_bf16.h>

#define T_LEN 4096
#define N_DIM 256
#define U_DIM 128
#define K_DIM 32
#define P_DIM 128
#define NK    8192   // N_DIM * K_DIM
#define CH_L  64     // chunk length
#define NCH   64     // number of chunks (T_LEN / CH_L)
#define G_T   16     // timesteps per k1 CTA

// ---------------- device scratch (no runtime allocation allowed) ----------------
__device__ float g_S_re[(size_t)T_LEN * NK];   // 134 MB
__device__ float g_S_im[(size_t)T_LEN * NK];   // 134 MB
__device__ float g_Ct_re[N_DIM * P_DIM];
__device__ float g_Ct_im[N_DIM * P_DIM];
__device__ float g_Dt[U_DIM * P_DIM];
__device__ float g_send_re[NCH * NK];
__device__ float g_send_im[NCH * NK];
__device__ float g_carry_re[NCH * NK];
__device__ float g_carry_im[NCH * NK];
__device__ float g_apow_re[CH_L * NK];
__device__ float g_apow_im[CH_L * NK];
// B weights pre-packed as m16n8k16 A-fragments (hi/lo bf16):
// index = h*32768 + (((mt*8 + s)*2 + hl)*32 + lane)*4 + r   (u32 each)
__device__ unsigned int g_Wfrag[2 * 16 * 8 * 2 * 32 * 4];

typedef unsigned long long u64;
typedef unsigned int u32;

// ---------------- packed f32x2 helpers (Blackwell FFMA2) ----------------
__device__ __forceinline__ u64 pack2(float x, float y) {
    u64 r;
    asm("mov.b64 %0, {%1, %2};" : "=l"(r) : "f"(x), "f"(y));
    return r;
}
__device__ __forceinline__ u64 ffma2(u64 a, u64 b, u64 c) {
    u64 d;
    asm("fma.rn.f32x2 %0, %1, %2, %3;" : "=l"(d) : "l"(a), "l"(b), "l"(c));
    return d;
}

// ---------------- bf16 helpers ----------------
__device__ __forceinline__ u32 pack_bf16(float lo, float hi) {   // lo -> bits[0:16)
    __nv_bfloat16 a = __float2bfloat16_rn(lo), b = __float2bfloat16_rn(hi);
    unsigned short ua = *(unsigned short*)&a, ub = *(unsigned short*)&b;
    return (u32)ua | ((u32)ub << 16);
}
__device__ __forceinline__ float bf16_hi(float f) {
    return __bfloat162float(__float2bfloat16_rn(f));
}

// mma.sync m16n8k16 row.col f32.bf16.bf16.f32
__device__ __forceinline__ void mma16816(float* c, const u32* a, const u32* b) {
    asm volatile(
        "mma.sync.aligned.m16n8k16.row.col.f32.bf16.bf16.f32 "
        "{%0,%1,%2,%3}, {%4,%5,%6,%7}, {%8,%9}, {%0,%1,%2,%3};"
        : "+f"(c[0]), "+f"(c[1]), "+f"(c[2]), "+f"(c[3])
        : "r"(a[0]), "r"(a[1]), "r"(a[2]), "r"(a[3]), "r"(b[0]), "r"(b[1]));
}

// ---------------- K0a: transpose small weight matrices (for k3) ----------------
__global__ __launch_bounds__(256) void k0_transpose(
    const float* __restrict__ Cre, const float* __restrict__ Cim,
    const float* __restrict__ D)
{
    int i = blockIdx.x * 256 + threadIdx.x;
    if (i < P_DIM * N_DIM) {           // C: (P,N) -> Ct: (N,P)
        int p = i / N_DIM, n = i % N_DIM;
        g_Ct_re[n * P_DIM + p] = Cre[i];
        g_Ct_im[n * P_DIM + p] = Cim[i];
    }
    if (i < P_DIM * U_DIM) {           // D: (P,U) -> Dt: (U,P)
        int p = i / U_DIM, u = i % U_DIM;
        g_Dt[u * P_DIM + p] = D[i];
    }
}

// ---------------- K0b: pack B weights into A-fragment layout (hi + lo) ---------
// work item = (h, mt, s, lane, r): 2*16*8*32*4 = 32768
__global__ __launch_bounds__(256) void k0_pack(
    const float* __restrict__ Bre, const float* __restrict__ Bim)
{
    int t = blockIdx.x * 256 + threadIdx.x;
    int r    = t & 3;
    int lane = (t >> 2) & 31;
    int s    = (t >> 7) & 7;
    int mt   = (t >> 10) & 15;
    int h    = t >> 14;
    int g = lane >> 2, c = lane & 3;
    int n = mt * 16 + g + ((r & 1) ? 8 : 0);
    int u = s * 16 + 2 * c + ((r & 2) ? 8 : 0);
    const float* W = h ? Bim : Bre;
    float f0 = W[n * U_DIM + u];
    float f1 = W[n * U_DIM + u + 1];
    float h0 = bf16_hi(f0), l0 = f0 - h0;
    float h1 = bf16_hi(f1), l1 = f1 - h1;
    int base = h * 32768 + ((mt * 8 + s) * 2) * 128 + lane * 4 + r;
    g_Wfrag[base]       = pack_bf16(h0, h1);   // hl = 0
    g_Wfrag[base + 128] = pack_bf16(l0, l1);   // hl = 1
}

// ---------------- K1 (HMMA): S[t,n,k] = sum_u B[n,u] * x[t,u,k] ----------------
// grid = (2 halves: re/im) x (T_LEN/G_T). CTA 256 threads (8 warps).
// warp w owns m-tiles {2w, 2w+1} (rows 32w..32w+31 of the 256-row half).
__global__ __launch_bounds__(256) void k1_mma(const float* __restrict__ x)
{
    extern __shared__ char sm[];
    float* Xs = (float*)sm;                          // [128][33] padded: 16896 B
    u32*   Wf = (u32*)(sm + 16896);                  // 32768 u32 = 131072 B
    u64*   Xf = (u64*)(sm + 16896 + 131072);         // 2048 u64 = 16384 B

    int tid = threadIdx.x;
    int w = tid >> 5, lane = tid & 31;
    int half = blockIdx.x;
    float* dst = half ? g_S_im : g_S_re;
    int t0 = blockIdx.y * G_T;

    // copy this half's weight fragments to smem (8192 float4)
    {
        const float4* src = (const float4*)(g_Wfrag + half * 32768);
        float4* d4 = (float4*)Wf;
#pragma unroll
        for (int i = 0; i < 32; i++) d4[tid + i * 256] = src[tid + i * 256];
    }

    int g = lane >> 2, c = lane & 3;

    for (int tt = 0; tt < G_T; tt++) {
        int t = t0 + tt;
        __syncthreads();   // protect Xs/Xf from previous iteration's readers
        // ---- stage x[t] into padded smem (coalesced 32-bit loads)
        const float* xp = x + (size_t)t * (U_DIM * K_DIM);
#pragma unroll
        for (int i = 0; i < 16; i++) {
            int e = tid + i * 256;
            Xs[(e >> 5) * 33 + (e & 31)] = xp[e];
        }
        __syncthreads();
        // ---- convert into B-fragment layout (hi/lo), 8 slots per thread
#pragma unroll
        for (int i = 0; i < 8; i++) {
            int slot = tid + i * 256;
            int sl = slot & 31;
            int hl = (slot >> 5) & 1;
            int nt = (slot >> 6) & 3;
            int s  = slot >> 8;
            int sg = sl >> 2, sc = sl & 3;
            int u0 = s * 16 + 2 * sc;
            int kc = nt * 8 + sg;
            float v0 = Xs[u0 * 33 + kc];
            float v1 = Xs[(u0 + 1) * 33 + kc];
            float v2 = Xs[(u0 + 8) * 33 + kc];
            float v3 = Xs[(u0 + 9) * 33 + kc];
            u32 b0, b1;
            if (hl == 0) {
                b0 = pack_bf16(bf16_hi(v0), bf16_hi(v1));
                b1 = pack_bf16(bf16_hi(v2), bf16_hi(v3));
            } else {
                b0 = pack_bf16(v0 - bf16_hi(v0), v1 - bf16_hi(v1));
                b1 = pack_bf16(v2 - bf16_hi(v2), v3 - bf16_hi(v3));
            }
            u64 pv;
            asm("mov.b64 %0, {%1, %2};" : "=l"(pv) : "r"(b0), "r"(b1));
            Xf[slot] = pv;
        }
        __syncthreads();
        // ---- HMMA mainloop
        float acc[2][4][4];
#pragma unroll
        for (int mtl = 0; mtl < 2; mtl++)
#pragma unroll
            for (int nt = 0; nt < 4; nt++)
#pragma unroll
                for (int q = 0; q < 4; q++) acc[mtl][nt][q] = 0.f;

        for (int s = 0; s < 8; s++) {
            u32 ah[2][4], al[2][4];
#pragma unroll
            for (int mtl = 0; mtl < 2; mtl++) {
                int mt = w * 2 + mtl;
                const uint4* ap = (const uint4*)(Wf + ((mt * 8 + s) * 2) * 128);
                uint4 vh = ap[lane];
                uint4 vl = ap[32 + lane];
                ah[mtl][0] = vh.x; ah[mtl][1] = vh.y; ah[mtl][2] = vh.z; ah[mtl][3] = vh.w;
                al[mtl][0] = vl.x; al[mtl][1] = vl.y; al[mtl][2] = vl.z; al[mtl][3] = vl.w;
            }
            u32 bh[4][2], bl[4][2];
#pragma unroll
            for (int nt = 0; nt < 4; nt++) {
                u64 vh = Xf[((s * 4 + nt) * 2 + 0) * 32 + lane];
                u64 vl = Xf[((s * 4 + nt) * 2 + 1) * 32 + lane];
                asm("mov.b64 {%0, %1}, %2;" : "=r"(bh[nt][0]), "=r"(bh[nt][1]) : "l"(vh));
                asm("mov.b64 {%0, %1}, %2;" : "=r"(bl[nt][0]), "=r"(bl[nt][1]) : "l"(vl));
            }
#pragma unroll
            for (int mtl = 0; mtl < 2; mtl++)
#pragma unroll
                for (int nt = 0; nt < 4; nt++) {
                    mma16816(acc[mtl][nt], ah[mtl], bh[nt]);
                    mma16816(acc[mtl][nt], ah[mtl], bl[nt]);
                    mma16816(acc[mtl][nt], al[mtl], bh[nt]);
                }
        }
        // ---- epilogue: write fp32 states
        size_t tb = (size_t)t * NK;
#pragma unroll
        for (int mtl = 0; mtl < 2; mtl++) {
            int nrow = (w * 2 + mtl) * 16 + g;
#pragma unroll
            for (int nt = 0; nt < 4; nt++) {
                int kc = nt * 8 + 2 * c;
                float2 lo = make_float2(acc[mtl][nt][0], acc[mtl][nt][1]);
                float2 hi = make_float2(acc[mtl][nt][2], acc[mtl][nt][3]);
                *(float2*)(dst + tb + nrow * K_DIM + kc) = lo;
                *(float2*)(dst + tb + (nrow + 8) * K_DIM + kc) = hi;
            }
        }
    }
}

// ---------------- K2a: local (per-chunk) scans, in place -----------------------
__global__ __launch_bounds__(256) void k2_local(
    const float* __restrict__ Are, const float* __restrict__ Aim)
{
    int c = blockIdx.x * 256 + threadIdx.x;   // chain = n*K + k
    int chunk = blockIdx.y;
    float ar = Are[c], ai = Aim[c];
    float sr = 0.f, si = 0.f;
    int base = chunk * CH_L * NK + c;
    for (int tg = 0; tg < CH_L; tg += 4) {
        float inr[4], ini[4];
#pragma unroll
        for (int j = 0; j < 4; j++) {
            inr[j] = g_S_re[base + j * NK];
            ini[j] = g_S_im[base + j * NK];
        }
#pragma unroll
        for (int j = 0; j < 4; j++) {
            float nr = fmaf(ar, sr, fmaf(-ai, si, inr[j]));
            float ni = fmaf(ar, si, fmaf(ai, sr, ini[j]));
            sr = nr; si = ni;
            g_S_re[base + j * NK] = sr;
            g_S_im[base + j * NK] = si;
        }
        base += 4 * NK;
    }
    g_send_re[chunk * NK + c] = sr;
    g_send_im[chunk * NK + c] = si;
}

// ---------------- K2b: power table + cross-chunk carries (prefetched) ----------
__global__ __launch_bounds__(256) void k2_carry(
    const float* __restrict__ Are, const float* __restrict__ Aim)
{
    int c = blockIdx.x * 256 + threadIdx.x;
    float ar = Are[c], ai = Aim[c];
    float qr = ar, qi = ai;
    float a64r = 0.f, a64i = 0.f;
    for (int j = 0; j < CH_L; j++) {
        g_apow_re[j * NK + c] = qr;
        g_apow_im[j * NK + c] = qi;
        if (j == CH_L - 1) { a64r = qr; a64i = qi; }
        float tmp = qr * ar - qi * ai;
        qi = qr * ai + qi * ar;
        qr = tmp;
    }
    float cr = 0.f, ci = 0.f;
    for (int ch = 0; ch < NCH; ch += 8) {
        float sr[8], si[8];
#pragma unroll
        for (int j = 0; j < 8; j++) {
            sr[j] = g_send_re[(ch + j) * NK + c];
            si[j] = g_send_im[(ch + j) * NK + c];
        }
#pragma unroll
        for (int j = 0; j < 8; j++) {
            g_carry_re[(ch + j) * NK + c] = cr;
            g_carry_im[(ch + j) * NK + c] = ci;
            float tmp = fmaf(a64r, cr, fmaf(-a64i, ci, sr[j]));
            ci = fmaf(a64r, ci, fmaf(a64i, cr, si[j]));
            cr = tmp;
        }
    }
}

// ---------------- K3: out[t,p,k] = Re(C @ s_t) + D @ x_t, scan fixup fused -----
__global__ __launch_bounds__(256) void k3_out(
    const float* __restrict__ x, float* __restrict__ out)
{
    extern __shared__ float smem[];
    float* Ssr = smem;              // 8192 floats
    float* Ssi = smem + 8192;       // 8192
    float* Xs  = smem + 16384;      // 4096
    float* Wre = smem + 20480;      // 4096
    float* Wim = smem + 24576;      // 4096

    int t = blockIdx.x;
    int tid = threadIdx.x;
    int chunk = t >> 6, tl = t & 63;
    int tb = t * NK;

#pragma unroll 4
    for (int ii = 0; ii < 32; ii++) {
        int i = tid + ii * 256;
        float lr = g_S_re[tb + i], li = g_S_im[tb + i];
        float pr = g_apow_re[tl * NK + i], pi = g_apow_im[tl * NK + i];
        float cr = g_carry_re[chunk * NK + i], ci = g_carry_im[chunk * NK + i];
        Ssr[i] = fmaf(pr, cr, fmaf(-pi, ci, lr));
        Ssi[i] = fmaf(pr, ci, fmaf(pi, cr, li));
    }
    const float4* xp = (const float4*)(x + (size_t)t * U_DIM * K_DIM);
    float4* xs4 = (float4*)Xs;
#pragma unroll
    for (int i = 0; i < 4; i++) xs4[tid + i * 256] = xp[tid + i * 256];

    int lane = tid & 31;
    int w = tid >> 5;
    int kh = w & 3;
    int ph = w >> 2;
    int kb = kh * 8;
    int pb = ph * 64 + lane;

    u64 acc[2][4];
#pragma unroll
    for (int j = 0; j < 2; j++)
#pragma unroll
        for (int q = 0; q < 4; q++) acc[j][q] = 0ull;

    for (int nt = 0; nt < 8; nt++) {
        __syncthreads();
        const float4* cr4 = (const float4*)(g_Ct_re + nt * 32 * P_DIM);
        const float4* ci4 = (const float4*)(g_Ct_im + nt * 32 * P_DIM);
#pragma unroll
        for (int i = 0; i < 4; i++) {
            ((float4*)Wre)[tid + i * 256] = cr4[tid + i * 256];
            ((float4*)Wim)[tid + i * 256] = ci4[tid + i * 256];
        }
        __syncthreads();
#pragma unroll
        for (int r = 0; r < 32; r++) {
            int n = nt * 32 + r;
            u64 svr[4], svi[4];
#pragma unroll
            for (int q = 0; q < 4; q++) {
                svr[q] = *(const u64*)&Ssr[n * K_DIM + kb + 2 * q];
                svi[q] = *(const u64*)&Ssi[n * K_DIM + kb + 2 * q];
            }
#pragma unroll
            for (int j = 0; j < 2; j++) {
                float crv = Wre[r * P_DIM + pb + 32 * j];
                float civ = Wim[r * P_DIM + pb + 32 * j];
                u64 c2r = pack2(crv, crv);
                u64 c2i = pack2(-civ, -civ);
#pragma unroll
                for (int q = 0; q < 4; q++) {
                    acc[j][q] = ffma2(c2r, svr[q], acc[j][q]);
                    acc[j][q] = ffma2(c2i, svi[q], acc[j][q]);
                }
            }
        }
    }

    for (int ut = 0; ut < 2; ut++) {
        __syncthreads();
        const float4* d4 = (const float4*)(g_Dt + ut * 64 * P_DIM);
#pragma unroll
        for (int i = 0; i < 8; i++)
            ((float4*)Wre)[tid + i * 256] = d4[tid + i * 256];
        __syncthreads();
#pragma unroll
        for (int r = 0; r < 64; r++) {
            int u = ut * 64 + r;
            u64 xv[4];
#pragma unroll
            for (int q = 0; q < 4; q++)
                xv[q] = *(const u64*)&Xs[u * K_DIM + kb + 2 * q];
#pragma unroll
            for (int j = 0; j < 2; j++) {
                float dv = Wre[r * P_DIM + pb + 32 * j];
                u64 d2 = pack2(dv, dv);
#pragma unroll
                for (int q = 0; q < 4; q++)
                    acc[j][q] = ffma2(d2, xv[q], acc[j][q]);
            }
        }
    }

    size_t ob = (size_t)t * P_DIM * K_DIM;
#pragma unroll
    for (int j = 0; j < 2; j++) {
        int p = pb + 32 * j;
#pragma unroll
        for (int q = 0; q < 4; q++)
            *(u64*)&out[ob + p * K_DIM + kb + 2 * q] = acc[j][q];
    }
}

// ---------------- launch ----------------
extern "C" void kernel_launch(void* const* d_in, const int* in_sizes, int n_in,
                              void* d_out, int out_size)
{
    const float* x   = (const float*)d_in[0];
    const float* Are = (const float*)d_in[1];
    const float* Aim = (const float*)d_in[2];
    const float* Bre = (const float*)d_in[3];
    const float* Bim = (const float*)d_in[4];
    const float* Cre = (const float*)d_in[5];
    const float* Cim = (const float*)d_in[6];
    const float* D   = (const float*)d_in[7];
    float* out = (float*)d_out;

    k0_transpose<<<128, 256>>>(Cre, Cim, D);
    k0_pack<<<128, 256>>>(Bre, Bim);

    cudaFuncSetAttribute(k1_mma, cudaFuncAttributeMaxDynamicSharedMemorySize, 164352);
    k1_mma<<<dim3(2, T_LEN / G_T), 256, 164352>>>(x);

    dim3 g2(NK / 256, NCH);
    k2_local<<<g2, 256>>>(Are, Aim);
    k2_carry<<<NK / 256, 256>>>(Are, Aim);

    cudaFuncSetAttribute(k3_out, cudaFuncAttributeMaxDynamicSharedMemorySize, 114688);
    k3_out<<<T_LEN, 256, 114688>>>(x, out);
}